// round 2
// baseline (speedup 1.0000x reference)
#include <cuda_runtime.h>

// ---------------------------------------------------------------------------
// BatchedGeometryComputation
//   out = [centroids (n_blocks*3) | rel (n_atoms*3) | dist (n_atoms) | rbf (n_atoms*16)]
// block_id is SORTED ascending -> run-compressed segment sums.
// ---------------------------------------------------------------------------

#define RBF_DIM 16
#define MAX_BLOCKS_SCRATCH 262144
#define ACC_CHUNK 32
#define ATOMS_PER_THREAD 2

// scratch: per-block (sum_x, sum_y, sum_z, count)
__device__ float4 g_sums[MAX_BLOCKS_SCRATCH];

__global__ void k_zero_sums(int n_blocks) {
    for (int i = blockIdx.x * blockDim.x + threadIdx.x; i < n_blocks;
         i += gridDim.x * blockDim.x)
        g_sums[i] = make_float4(0.f, 0.f, 0.f, 0.f);
}

// Each logical worker owns ACC_CHUNK contiguous atoms; flush on block-id change.
__global__ void k_accum(const float* __restrict__ pos,
                        const int* __restrict__ bid,
                        int n_atoms, int n_workers) {
    for (int w = blockIdx.x * blockDim.x + threadIdx.x; w < n_workers;
         w += gridDim.x * blockDim.x) {
        int s = w * ACC_CHUNK;
        int e = (n_atoms - s < ACC_CHUNK) ? n_atoms : s + ACC_CHUNK;

        int cur = bid[s];
        float sx = 0.f, sy = 0.f, sz = 0.f, cnt = 0.f;
        for (int i = s; i < e; ++i) {
            int b = bid[i];
            if (b != cur) {
                float* p = (float*)&g_sums[cur];
                atomicAdd(p + 0, sx);
                atomicAdd(p + 1, sy);
                atomicAdd(p + 2, sz);
                atomicAdd(p + 3, cnt);
                cur = b; sx = sy = sz = 0.f; cnt = 0.f;
            }
            sx += pos[3 * i + 0];
            sy += pos[3 * i + 1];
            sz += pos[3 * i + 2];
            cnt += 1.f;
        }
        float* p = (float*)&g_sums[cur];
        atomicAdd(p + 0, sx);
        atomicAdd(p + 1, sy);
        atomicAdd(p + 2, sz);
        atomicAdd(p + 3, cnt);
    }
}

__global__ void k_centroid(float* __restrict__ out_c, int n_blocks) {
    for (int i = blockIdx.x * blockDim.x + threadIdx.x; i < n_blocks;
         i += gridDim.x * blockDim.x) {
        float4 s = g_sums[i];
        float inv = 1.f / fmaxf(s.w, 1.f);
        out_c[3 * i + 0] = s.x * inv;
        out_c[3 * i + 1] = s.y * inv;
        out_c[3 * i + 2] = s.z * inv;
    }
}

// ATOMS_PER_THREAD atoms per thread: rel pos, distance, 16-wide RBF (float4 stores).
__global__ void k_atoms(const float* __restrict__ pos,
                        const int* __restrict__ bid,
                        const float* __restrict__ centers,
                        const float* __restrict__ widths,
                        const float* __restrict__ cent,   // [n_blocks*3]
                        float* __restrict__ out_rel,
                        float* __restrict__ out_dist,
                        float4* __restrict__ out_rbf,     // n_atoms * 4 float4
                        int n_atoms) {
    __shared__ float s_c[RBF_DIM];
    __shared__ float s_iw[RBF_DIM];
    if (threadIdx.x < RBF_DIM) {
        s_c[threadIdx.x] = centers[threadIdx.x];
        float w = widths[threadIdx.x];
        s_iw[threadIdx.x] = 1.f / (2.f * w * w);
    }
    __syncthreads();

    int tid     = blockIdx.x * blockDim.x + threadIdx.x;
    int nthread = gridDim.x * blockDim.x;

    for (long long base = (long long)tid * ATOMS_PER_THREAD;
         base < n_atoms;
         base += (long long)nthread * ATOMS_PER_THREAD) {
        int i0   = (int)base;
        int nloc = (n_atoms - i0 < ATOMS_PER_THREAD) ? (n_atoms - i0) : ATOMS_PER_THREAD;

        // front-batch all global loads for both atoms (MLP)
        float px[ATOMS_PER_THREAD], py[ATOMS_PER_THREAD], pz[ATOMS_PER_THREAD];
        float cx[ATOMS_PER_THREAD], cy[ATOMS_PER_THREAD], cz[ATOMS_PER_THREAD];
#pragma unroll
        for (int a = 0; a < ATOMS_PER_THREAD; ++a) {
            if (a < nloc) {
                int i = i0 + a;
                int b = bid[i];
                px[a] = pos[3 * i + 0];
                py[a] = pos[3 * i + 1];
                pz[a] = pos[3 * i + 2];
                cx[a] = cent[3 * b + 0];
                cy[a] = cent[3 * b + 1];
                cz[a] = cent[3 * b + 2];
            }
        }

#pragma unroll
        for (int a = 0; a < ATOMS_PER_THREAD; ++a) {
            if (a < nloc) {
                int i = i0 + a;
                float rx = px[a] - cx[a];
                float ry = py[a] - cy[a];
                float rz = pz[a] - cz[a];

                out_rel[3 * i + 0] = rx;
                out_rel[3 * i + 1] = ry;
                out_rel[3 * i + 2] = rz;

                float d = sqrtf(rx * rx + ry * ry + rz * rz);
                out_dist[i] = d;

                float4 r[RBF_DIM / 4];
                float* rf = (float*)r;
#pragma unroll
                for (int k = 0; k < RBF_DIM; ++k) {
                    float t = d - s_c[k];
                    rf[k] = __expf(-t * t * s_iw[k]);
                }
                size_t rb = (size_t)i * (RBF_DIM / 4);
#pragma unroll
                for (int q = 0; q < RBF_DIM / 4; ++q) out_rbf[rb + q] = r[q];
            }
        }
    }
}

static inline int clamp_grid(long long b) {
    if (b < 1) return 1;
    if (b > 1048576) return 1048576;
    return (int)b;
}

extern "C" void kernel_launch(void* const* d_in, const int* in_sizes, int n_in,
                              void* d_out, int out_size) {
    const float* pos     = (const float*)d_in[0];  // [n_atoms*3]
    const int*   bid     = (const int*)d_in[1];    // [n_atoms]
    // d_in[2] = n_blocks scalar on device; derive arithmetically (no sync copies)
    const float* centers = (const float*)d_in[3];  // [16]
    const float* widths  = (const float*)d_in[4];  // [16]

    int n_atoms  = in_sizes[0] / 3;
    long long nb = ((long long)out_size - (long long)n_atoms * (3 + 1 + RBF_DIM)) / 3;
    int n_blocks = (int)nb;
    if (n_blocks < 1) n_blocks = 1;
    if (n_blocks > MAX_BLOCKS_SCRATCH) n_blocks = MAX_BLOCKS_SCRATCH;

    float* out      = (float*)d_out;
    float* out_cent = out;                                    // n_blocks*3
    float* out_rel  = out + (size_t)n_blocks * 3;             // n_atoms*3
    float* out_dist = out_rel + (size_t)n_atoms * 3;          // n_atoms
    float4* out_rbf = (float4*)(out_dist + (size_t)n_atoms);  // n_atoms*16 floats

    // 1) zero scratch
    k_zero_sums<<<clamp_grid((n_blocks + 255) / 256), 256>>>(n_blocks);

    // 2) segment sums (run-compressed atomics)
    int n_workers = (n_atoms + ACC_CHUNK - 1) / ACC_CHUNK;
    k_accum<<<clamp_grid((n_workers + 255) / 256), 256>>>(pos, bid, n_atoms, n_workers);

    // 3) centroids
    k_centroid<<<clamp_grid((n_blocks + 255) / 256), 256>>>(out_cent, n_blocks);

    // 4) per-atom rel/dist/rbf
    long long work = ((long long)n_atoms + ATOMS_PER_THREAD - 1) / ATOMS_PER_THREAD;
    k_atoms<<<clamp_grid((work + 255) / 256), 256>>>(
        pos, bid, centers, widths, out_cent, out_rel, out_dist, out_rbf, n_atoms);
}

// round 4
// speedup vs baseline: 1.7840x; 1.7840x over previous
#include <cuda_runtime.h>

// ---------------------------------------------------------------------------
// BatchedGeometryComputation
//   out = [centroids (n_blocks*3) | rel (n_atoms*3) | dist (n_atoms) | rbf (n_atoms*16)]
// block_id is SORTED ascending.
// ---------------------------------------------------------------------------

#define RBF_DIM 16
#define MAX_BLOCKS_SCRATCH 262144

// scratch: per-block (sum_x, sum_y, sum_z, count)
__device__ float4 g_sums[MAX_BLOCKS_SCRATCH];

__global__ void k_zero_sums(int n_blocks) {
    for (int i = blockIdx.x * blockDim.x + threadIdx.x; i < n_blocks;
         i += gridDim.x * blockDim.x)
        g_sums[i] = make_float4(0.f, 0.f, 0.f, 0.f);
}

// One atom per lane (coalesced). Warp-level segmented reduction over the
// sorted block ids: shfl-down doubling guarded by key equality; only segment
// heads (~1.8 per warp on average) issue atomics.
__global__ void k_accum(const float* __restrict__ pos,
                        const int* __restrict__ bid,
                        int n_atoms) {
    int i    = blockIdx.x * blockDim.x + threadIdx.x;
    int lane = threadIdx.x & 31;

    bool valid = i < n_atoms;
    int idx = valid ? i : (n_atoms - 1);

    int   b   = bid[idx];
    float sx  = valid ? pos[3 * idx + 0] : 0.f;
    float sy  = valid ? pos[3 * idx + 1] : 0.f;
    float sz  = valid ? pos[3 * idx + 2] : 0.f;
    float cnt = valid ? 1.f : 0.f;

    // segmented suffix-reduce within warp (keys sorted -> runs contiguous)
#pragma unroll
    for (int off = 1; off < 32; off <<= 1) {
        int   ob = __shfl_down_sync(0xffffffffu, b, off);
        float ox = __shfl_down_sync(0xffffffffu, sx, off);
        float oy = __shfl_down_sync(0xffffffffu, sy, off);
        float oz = __shfl_down_sync(0xffffffffu, sz, off);
        float oc = __shfl_down_sync(0xffffffffu, cnt, off);
        if (lane + off < 32 && ob == b) {
            sx += ox; sy += oy; sz += oz; cnt += oc;
        }
    }

    // head lanes: lane 0, or previous lane has a different key
    int prev_b = __shfl_up_sync(0xffffffffu, b, 1);
    bool head = (lane == 0) || (prev_b != b);
    if (head && cnt > 0.f) {
        float* p = (float*)&g_sums[b];
        atomicAdd(p + 0, sx);
        atomicAdd(p + 1, sy);
        atomicAdd(p + 2, sz);
        atomicAdd(p + 3, cnt);
    }
}

__global__ void k_centroid(float* __restrict__ out_c, int n_blocks) {
    for (int i = blockIdx.x * blockDim.x + threadIdx.x; i < n_blocks;
         i += gridDim.x * blockDim.x) {
        float4 s = g_sums[i];
        float inv = 1.f / fmaxf(s.w, 1.f);
        out_c[3 * i + 0] = s.x * inv;
        out_c[3 * i + 1] = s.y * inv;
        out_c[3 * i + 2] = s.z * inv;
    }
}

// One atom per thread. Centroid gathered as ONE float4 from g_sums (divide
// inline, removes dependency on k_centroid's output). Streaming stores for
// all write-once outputs. RBF computed/stored in two 8-wide halves to cap
// register liveness and keep occupancy high.
__global__ void __launch_bounds__(256, 6)
k_atoms(const float* __restrict__ pos,
        const int* __restrict__ bid,
        const float* __restrict__ centers,
        const float* __restrict__ widths,
        float* __restrict__ out_rel,
        float* __restrict__ out_dist,
        float4* __restrict__ out_rbf,     // n_atoms * 4 float4
        int n_atoms) {
    __shared__ float s_c[RBF_DIM];
    __shared__ float s_iw[RBF_DIM];
    if (threadIdx.x < RBF_DIM) {
        s_c[threadIdx.x] = centers[threadIdx.x];
        float w = widths[threadIdx.x];
        s_iw[threadIdx.x] = 1.f / (2.f * w * w);
    }
    __syncthreads();

    int i = blockIdx.x * blockDim.x + threadIdx.x;
    if (i >= n_atoms) return;

    int b = bid[i];
    float4 s = g_sums[b];                       // single LDG.128, L2-resident
    float inv = 1.f / fmaxf(s.w, 1.f);

    float rx = pos[3 * i + 0] - s.x * inv;
    float ry = pos[3 * i + 1] - s.y * inv;
    float rz = pos[3 * i + 2] - s.z * inv;

    __stcs(&out_rel[3 * i + 0], rx);
    __stcs(&out_rel[3 * i + 1], ry);
    __stcs(&out_rel[3 * i + 2], rz);

    float d = sqrtf(rx * rx + ry * ry + rz * rz);
    __stcs(&out_dist[i], d);

    size_t rb = (size_t)i * (RBF_DIM / 4);

    // first half: k = 0..7
    {
        float4 v0, v1;
        float t;
        t = d - s_c[0]; v0.x = __expf(-t * t * s_iw[0]);
        t = d - s_c[1]; v0.y = __expf(-t * t * s_iw[1]);
        t = d - s_c[2]; v0.z = __expf(-t * t * s_iw[2]);
        t = d - s_c[3]; v0.w = __expf(-t * t * s_iw[3]);
        t = d - s_c[4]; v1.x = __expf(-t * t * s_iw[4]);
        t = d - s_c[5]; v1.y = __expf(-t * t * s_iw[5]);
        t = d - s_c[6]; v1.z = __expf(-t * t * s_iw[6]);
        t = d - s_c[7]; v1.w = __expf(-t * t * s_iw[7]);
        __stcs(&out_rbf[rb + 0], v0);
        __stcs(&out_rbf[rb + 1], v1);
    }
    // second half: k = 8..15
    {
        float4 v0, v1;
        float t;
        t = d - s_c[8];  v0.x = __expf(-t * t * s_iw[8]);
        t = d - s_c[9];  v0.y = __expf(-t * t * s_iw[9]);
        t = d - s_c[10]; v0.z = __expf(-t * t * s_iw[10]);
        t = d - s_c[11]; v0.w = __expf(-t * t * s_iw[11]);
        t = d - s_c[12]; v1.x = __expf(-t * t * s_iw[12]);
        t = d - s_c[13]; v1.y = __expf(-t * t * s_iw[13]);
        t = d - s_c[14]; v1.z = __expf(-t * t * s_iw[14]);
        t = d - s_c[15]; v1.w = __expf(-t * t * s_iw[15]);
        __stcs(&out_rbf[rb + 2], v0);
        __stcs(&out_rbf[rb + 3], v1);
    }
}

static inline int clamp_grid(long long b) {
    if (b < 1) return 1;
    if (b > 1048576) return 1048576;
    return (int)b;
}

extern "C" void kernel_launch(void* const* d_in, const int* in_sizes, int n_in,
                              void* d_out, int out_size) {
    const float* pos     = (const float*)d_in[0];  // [n_atoms*3]
    const int*   bid     = (const int*)d_in[1];    // [n_atoms]
    // d_in[2] = n_blocks scalar on device; derive arithmetically (no sync copies)
    const float* centers = (const float*)d_in[3];  // [16]
    const float* widths  = (const float*)d_in[4];  // [16]

    int n_atoms  = in_sizes[0] / 3;
    long long nb = ((long long)out_size - (long long)n_atoms * (3 + 1 + RBF_DIM)) / 3;
    int n_blocks = (int)nb;
    if (n_blocks < 1) n_blocks = 1;
    if (n_blocks > MAX_BLOCKS_SCRATCH) n_blocks = MAX_BLOCKS_SCRATCH;

    float* out      = (float*)d_out;
    float* out_cent = out;                                    // n_blocks*3
    float* out_rel  = out + (size_t)n_blocks * 3;             // n_atoms*3
    float* out_dist = out_rel + (size_t)n_atoms * 3;          // n_atoms
    float4* out_rbf = (float4*)(out_dist + (size_t)n_atoms);  // n_atoms*16 floats

    // 1) zero scratch
    k_zero_sums<<<clamp_grid((n_blocks + 255) / 256), 256>>>(n_blocks);

    // 2) segment sums (coalesced, warp-aggregated atomics)
    if (n_atoms > 0)
        k_accum<<<clamp_grid(((long long)n_atoms + 255) / 256), 256>>>(pos, bid, n_atoms);

    // 3) centroids output
    k_centroid<<<clamp_grid((n_blocks + 255) / 256), 256>>>(out_cent, n_blocks);

    // 4) per-atom rel/dist/rbf (reads g_sums directly; independent of step 3)
    if (n_atoms > 0)
        k_atoms<<<clamp_grid(((long long)n_atoms + 255) / 256), 256>>>(
            pos, bid, centers, widths, out_rel, out_dist, out_rbf, n_atoms);
}

// round 6
// speedup vs baseline: 1.8494x; 1.0367x over previous
#include <cuda_runtime.h>

// ---------------------------------------------------------------------------
// BatchedGeometryComputation
//   out = [centroids (n_blocks*3) | rel (n_atoms*3) | dist (n_atoms) | rbf (n_atoms*16)]
// block_id is SORTED ascending.
// ---------------------------------------------------------------------------

#define RBF_DIM 16
#define MAX_BLOCKS_SCRATCH 262144
#define TPB 256

// scratch: per-block (sum_x, sum_y, sum_z, count)
__device__ float4 g_sums[MAX_BLOCKS_SCRATCH];

__global__ void k_zero_sums(int n_blocks) {
    for (int i = blockIdx.x * blockDim.x + threadIdx.x; i < n_blocks;
         i += gridDim.x * blockDim.x)
        g_sums[i] = make_float4(0.f, 0.f, 0.f, 0.f);
}

// One atom per lane (coalesced). Warp-level segmented reduction over the
// sorted block ids; only segment heads issue atomics.
__global__ void k_accum(const float* __restrict__ pos,
                        const int* __restrict__ bid,
                        int n_atoms) {
    int i    = blockIdx.x * blockDim.x + threadIdx.x;
    int lane = threadIdx.x & 31;

    bool valid = i < n_atoms;
    int idx = valid ? i : (n_atoms - 1);

    int   b   = bid[idx];
    float sx  = valid ? pos[3 * idx + 0] : 0.f;
    float sy  = valid ? pos[3 * idx + 1] : 0.f;
    float sz  = valid ? pos[3 * idx + 2] : 0.f;
    float cnt = valid ? 1.f : 0.f;

#pragma unroll
    for (int off = 1; off < 32; off <<= 1) {
        int   ob = __shfl_down_sync(0xffffffffu, b, off);
        float ox = __shfl_down_sync(0xffffffffu, sx, off);
        float oy = __shfl_down_sync(0xffffffffu, sy, off);
        float oz = __shfl_down_sync(0xffffffffu, sz, off);
        float oc = __shfl_down_sync(0xffffffffu, cnt, off);
        if (lane + off < 32 && ob == b) {
            sx += ox; sy += oy; sz += oz; cnt += oc;
        }
    }

    int prev_b = __shfl_up_sync(0xffffffffu, b, 1);
    bool head = (lane == 0) || (prev_b != b);
    if (head && cnt > 0.f) {
        float* p = (float*)&g_sums[b];
        atomicAdd(p + 0, sx);
        atomicAdd(p + 1, sy);
        atomicAdd(p + 2, sz);
        atomicAdd(p + 3, cnt);
    }
}

__global__ void k_centroid(float* __restrict__ out_c, int n_blocks) {
    for (int i = blockIdx.x * blockDim.x + threadIdx.x; i < n_blocks;
         i += gridDim.x * blockDim.x) {
        float4 s = g_sums[i];
        float inv = 1.f / fmaxf(s.w, 1.f);
        out_c[3 * i + 0] = s.x * inv;
        out_c[3 * i + 1] = s.y * inv;
        out_c[3 * i + 2] = s.z * inv;
    }
}

// One atom per thread, block = TPB atoms. pos is loaded cooperatively as
// float4 into shared (3 L1 wavefronts/warp vs 9 scalar), rel is written back
// into the SAME shared slots (self-overwrite, no hazard) and stored
// cooperatively as float4 streaming stores. Stride-3 shared reads are
// bank-conflict-free (gcd(3,32)=1).
__global__ void __launch_bounds__(TPB, 6)
k_atoms(const float* __restrict__ pos,
        const int* __restrict__ bid,
        const float* __restrict__ centers,
        const float* __restrict__ widths,
        float* __restrict__ out_rel,
        float* __restrict__ out_dist,
        float4* __restrict__ out_rbf,     // n_atoms * 4 float4
        int n_atoms) {
    __shared__ float s_c[RBF_DIM];
    __shared__ float s_iw[RBF_DIM];
    __shared__ float s_xyz[3 * TPB];      // staged pos, then reused for rel

    int t = threadIdx.x;
    if (t < RBF_DIM) {
        s_c[t] = centers[t];
        float w = widths[t];
        s_iw[t] = 1.f / (2.f * w * w);
    }

    int a0 = blockIdx.x * TPB;            // first atom of this block
    bool full = (a0 + TPB) <= n_atoms;

    // ---- stage pos into shared ----
    if (full) {
        // 3*TPB floats = (3*TPB/4) float4 loads; base index 3*a0 is /4-divisible
        const float4* p4 = (const float4*)(pos + (size_t)3 * a0);
        if (t < (3 * TPB / 4)) ((float4*)s_xyz)[t] = p4[t];
    } else {
        for (int k = t; k < 3 * TPB; k += TPB) {
            int gi = 3 * a0 + k;
            s_xyz[k] = (gi < 3 * n_atoms) ? pos[gi] : 0.f;
        }
    }
    __syncthreads();

    int i = a0 + t;
    float d = 0.f;
    bool act = i < n_atoms;

    if (act) {
        int b = bid[i];
        float4 s = g_sums[b];             // single LDG.128, L2/L1-broadcast
        float inv = 1.f / fmaxf(s.w, 1.f);

        float rx = s_xyz[3 * t + 0] - s.x * inv;
        float ry = s_xyz[3 * t + 1] - s.y * inv;
        float rz = s_xyz[3 * t + 2] - s.z * inv;

        // write rel back into own slots (no cross-thread hazard)
        s_xyz[3 * t + 0] = rx;
        s_xyz[3 * t + 1] = ry;
        s_xyz[3 * t + 2] = rz;

        d = sqrtf(rx * rx + ry * ry + rz * rz);
        __stcs(&out_dist[i], d);
    }
    __syncthreads();

    // ---- cooperative rel store ----
    if (full) {
        float4* r4 = (float4*)(out_rel + (size_t)3 * a0);
        if (t < (3 * TPB / 4)) __stcs(&r4[t], ((const float4*)s_xyz)[t]);
    } else {
        for (int k = t; k < 3 * TPB; k += TPB) {
            int gi = 3 * a0 + k;
            if (gi < 3 * n_atoms) out_rel[gi] = s_xyz[k];
        }
    }

    if (!act) return;

    size_t rb = (size_t)i * (RBF_DIM / 4);

    // RBF in two 8-wide halves to cap register liveness
    {
        float4 v0, v1;
        float u;
        u = d - s_c[0]; v0.x = __expf(-u * u * s_iw[0]);
        u = d - s_c[1]; v0.y = __expf(-u * u * s_iw[1]);
        u = d - s_c[2]; v0.z = __expf(-u * u * s_iw[2]);
        u = d - s_c[3]; v0.w = __expf(-u * u * s_iw[3]);
        u = d - s_c[4]; v1.x = __expf(-u * u * s_iw[4]);
        u = d - s_c[5]; v1.y = __expf(-u * u * s_iw[5]);
        u = d - s_c[6]; v1.z = __expf(-u * u * s_iw[6]);
        u = d - s_c[7]; v1.w = __expf(-u * u * s_iw[7]);
        __stcs(&out_rbf[rb + 0], v0);
        __stcs(&out_rbf[rb + 1], v1);
    }
    {
        float4 v0, v1;
        float u;
        u = d - s_c[8];  v0.x = __expf(-u * u * s_iw[8]);
        u = d - s_c[9];  v0.y = __expf(-u * u * s_iw[9]);
        u = d - s_c[10]; v0.z = __expf(-u * u * s_iw[10]);
        u = d - s_c[11]; v0.w = __expf(-u * u * s_iw[11]);
        u = d - s_c[12]; v1.x = __expf(-u * u * s_iw[12]);
        u = d - s_c[13]; v1.y = __expf(-u * u * s_iw[13]);
        u = d - s_c[14]; v1.z = __expf(-u * u * s_iw[14]);
        u = d - s_c[15]; v1.w = __expf(-u * u * s_iw[15]);
        __stcs(&out_rbf[rb + 2], v0);
        __stcs(&out_rbf[rb + 3], v1);
    }
}

static inline int clamp_grid(long long b) {
    if (b < 1) return 1;
    if (b > 1048576) return 1048576;
    return (int)b;
}

extern "C" void kernel_launch(void* const* d_in, const int* in_sizes, int n_in,
                              void* d_out, int out_size) {
    const float* pos     = (const float*)d_in[0];  // [n_atoms*3]
    const int*   bid     = (const int*)d_in[1];    // [n_atoms]
    // d_in[2] = n_blocks scalar on device; derive arithmetically (no sync copies)
    const float* centers = (const float*)d_in[3];  // [16]
    const float* widths  = (const float*)d_in[4];  // [16]

    int n_atoms  = in_sizes[0] / 3;
    long long nb = ((long long)out_size - (long long)n_atoms * (3 + 1 + RBF_DIM)) / 3;
    int n_blocks = (int)nb;
    if (n_blocks < 1) n_blocks = 1;
    if (n_blocks > MAX_BLOCKS_SCRATCH) n_blocks = MAX_BLOCKS_SCRATCH;

    float* out      = (float*)d_out;
    float* out_cent = out;                                    // n_blocks*3
    float* out_rel  = out + (size_t)n_blocks * 3;             // n_atoms*3
    float* out_dist = out_rel + (size_t)n_atoms * 3;          // n_atoms
    float4* out_rbf = (float4*)(out_dist + (size_t)n_atoms);  // n_atoms*16 floats

    // 1) zero scratch
    k_zero_sums<<<clamp_grid((n_blocks + 255) / 256), 256>>>(n_blocks);

    // 2) segment sums (coalesced, warp-aggregated atomics)
    if (n_atoms > 0)
        k_accum<<<clamp_grid(((long long)n_atoms + 255) / 256), 256>>>(pos, bid, n_atoms);

    // 3) centroids output
    k_centroid<<<clamp_grid((n_blocks + 255) / 256), 256>>>(out_cent, n_blocks);

    // 4) per-atom rel/dist/rbf (reads g_sums directly)
    if (n_atoms > 0)
        k_atoms<<<clamp_grid(((long long)n_atoms + TPB - 1) / TPB), TPB>>>(
            pos, bid, centers, widths, out_rel, out_dist, out_rbf, n_atoms);
}